// round 1
// baseline (speedup 1.0000x reference)
#include <cuda_runtime.h>
#include <cstdint>

#define B_TOTAL 1024
#define GROUPS  2048
#define KDIM    64
#define BT      64
#define STRIDE  68   // smem row stride in 32-bit words; bank = (4*row + col) % 32 -> conflict-free frag loads

__device__ __forceinline__ uint32_t f2tf32(float f) {
    uint32_t u;
    asm("cvt.rna.tf32.f32 %0, %1;" : "=r"(u) : "f"(f));
    return u;
}

__device__ __forceinline__ void mma_tf32(float& d0, float& d1, float& d2, float& d3,
                                         uint32_t a0, uint32_t a1, uint32_t a2, uint32_t a3,
                                         uint32_t b0, uint32_t b1) {
    asm volatile("mma.sync.aligned.m16n8k8.row.col.f32.tf32.tf32.f32 "
                 "{%0,%1,%2,%3}, {%4,%5,%6,%7}, {%8,%9}, {%0,%1,%2,%3};"
                 : "+f"(d0), "+f"(d1), "+f"(d2), "+f"(d3)
                 : "r"(a0), "r"(a1), "r"(a2), "r"(a3), "r"(b0), "r"(b1));
}

__global__ __launch_bounds__(256, 1) void convnn_tf32_kernel(
    const float* __restrict__ x,  const float* __restrict__ W0,
    const float* __restrict__ b0, const float* __restrict__ W1,
    const float* __restrict__ b1, float* __restrict__ out)
{
    __shared__ uint32_t sA[BT * STRIDE];   // X tile (tf32), then h tile (tf32)
    __shared__ uint32_t sW[64 * STRIDE];   // W0 (tf32), then W1 (tf32)
    __shared__ float    sB0[64];
    __shared__ float    sB1[64];

    const int g     = blockIdx.y;
    const int btile = blockIdx.x;
    const int tid   = threadIdx.x;
    const int lane  = tid & 31;
    const int warp  = tid >> 5;
    const int gid   = lane >> 2;   // 0..7
    const int tig   = lane & 3;    // 0..3

    // ---- cooperative load: X tile + W0 (converted to tf32) + biases ----
    {
        const int r  = tid >> 4;          // 0..15
        const int c4 = (tid & 15) << 2;   // 0,4,...,60
        const float* W0g = W0 + (size_t)g * 64 * KDIM;
        #pragma unroll
        for (int rr = 0; rr < 4; rr++) {
            const int row = r + rr * 16;
            float4 v = *(const float4*)(x + (size_t)(btile * BT + row) * KDIM + c4);
            uint32_t* da = &sA[row * STRIDE + c4];
            da[0] = f2tf32(v.x); da[1] = f2tf32(v.y);
            da[2] = f2tf32(v.z); da[3] = f2tf32(v.w);
            float4 w = *(const float4*)(W0g + (size_t)row * KDIM + c4);
            uint32_t* dw = &sW[row * STRIDE + c4];
            dw[0] = f2tf32(w.x); dw[1] = f2tf32(w.y);
            dw[2] = f2tf32(w.z); dw[3] = f2tf32(w.w);
        }
        if (tid < 64)       sB0[tid]      = b0[(size_t)g * 64 + tid];
        else if (tid < 128) sB1[tid - 64] = b1[(size_t)g * 64 + (tid - 64)];
    }
    __syncthreads();

    const int bRow0 = (warp & 3) * 16;   // 4 b-sub-tiles of 16
    const int jCol0 = (warp >> 2) * 32;  // 2 j-halves of 32

    float acc[4][4];

    // ================= Layer 0: h = leaky(X * W0^T + b0) =================
    #pragma unroll
    for (int s = 0; s < 4; s++)
        #pragma unroll
        for (int i = 0; i < 4; i++) acc[s][i] = 0.f;

    #pragma unroll
    for (int kc = 0; kc < 8; kc++) {
        const int k0 = kc * 8;
        const uint32_t a0 = sA[(bRow0 + gid)     * STRIDE + k0 + tig];
        const uint32_t a1 = sA[(bRow0 + gid + 8) * STRIDE + k0 + tig];
        const uint32_t a2 = sA[(bRow0 + gid)     * STRIDE + k0 + tig + 4];
        const uint32_t a3 = sA[(bRow0 + gid + 8) * STRIDE + k0 + tig + 4];
        #pragma unroll
        for (int s = 0; s < 4; s++) {
            const int j0 = jCol0 + s * 8;
            const uint32_t bb0 = sW[(j0 + gid) * STRIDE + k0 + tig];
            const uint32_t bb1 = sW[(j0 + gid) * STRIDE + k0 + tig + 4];
            mma_tf32(acc[s][0], acc[s][1], acc[s][2], acc[s][3],
                     a0, a1, a2, a3, bb0, bb1);
        }
    }
    __syncthreads();  // all mma reads of sA/sW complete

    // epilogue 0: bias + LeakyReLU(0.2), write h (tf32) into sA
    #pragma unroll
    for (int s = 0; s < 4; s++) {
        const int j0 = jCol0 + s * 8 + 2 * tig;
        const float bj0 = sB0[j0], bj1 = sB0[j0 + 1];
        float h00 = acc[s][0] + bj0; h00 = (h00 > 0.f) ? h00 : 0.2f * h00;
        float h01 = acc[s][1] + bj1; h01 = (h01 > 0.f) ? h01 : 0.2f * h01;
        float h10 = acc[s][2] + bj0; h10 = (h10 > 0.f) ? h10 : 0.2f * h10;
        float h11 = acc[s][3] + bj1; h11 = (h11 > 0.f) ? h11 : 0.2f * h11;
        sA[(bRow0 + gid)     * STRIDE + j0]     = f2tf32(h00);
        sA[(bRow0 + gid)     * STRIDE + j0 + 1] = f2tf32(h01);
        sA[(bRow0 + gid + 8) * STRIDE + j0]     = f2tf32(h10);
        sA[(bRow0 + gid + 8) * STRIDE + j0 + 1] = f2tf32(h11);
    }

    // load W1 (tf32) into sW
    {
        const int r  = tid >> 4;
        const int c4 = (tid & 15) << 2;
        const float* W1g = W1 + (size_t)g * 64 * KDIM;
        #pragma unroll
        for (int rr = 0; rr < 4; rr++) {
            const int row = r + rr * 16;
            float4 w = *(const float4*)(W1g + (size_t)row * KDIM + c4);
            uint32_t* dw = &sW[row * STRIDE + c4];
            dw[0] = f2tf32(w.x); dw[1] = f2tf32(w.y);
            dw[2] = f2tf32(w.z); dw[3] = f2tf32(w.w);
        }
    }
    __syncthreads();  // h + W1 visible

    // ================= Layer 1: out = h * W1^T + b1 =================
    #pragma unroll
    for (int s = 0; s < 4; s++)
        #pragma unroll
        for (int i = 0; i < 4; i++) acc[s][i] = 0.f;

    #pragma unroll
    for (int kc = 0; kc < 8; kc++) {
        const int k0 = kc * 8;
        const uint32_t a0 = sA[(bRow0 + gid)     * STRIDE + k0 + tig];
        const uint32_t a1 = sA[(bRow0 + gid + 8) * STRIDE + k0 + tig];
        const uint32_t a2 = sA[(bRow0 + gid)     * STRIDE + k0 + tig + 4];
        const uint32_t a3 = sA[(bRow0 + gid + 8) * STRIDE + k0 + tig + 4];
        #pragma unroll
        for (int s = 0; s < 4; s++) {
            const int j0 = jCol0 + s * 8;
            const uint32_t bb0 = sW[(j0 + gid) * STRIDE + k0 + tig];
            const uint32_t bb1 = sW[(j0 + gid) * STRIDE + k0 + tig + 4];
            mma_tf32(acc[s][0], acc[s][1], acc[s][2], acc[s][3],
                     a0, a1, a2, a3, bb0, bb1);
        }
    }

    // epilogue 1: bias, write out as float2 (32B sectors per (b,g) row)
    const int bglob = btile * BT + bRow0 + gid;
    #pragma unroll
    for (int s = 0; s < 4; s++) {
        const int j0 = jCol0 + s * 8 + 2 * tig;
        const float bj0 = sB1[j0], bj1 = sB1[j0 + 1];
        float2 v0 = make_float2(acc[s][0] + bj0, acc[s][1] + bj1);
        float2 v1 = make_float2(acc[s][2] + bj0, acc[s][3] + bj1);
        *(float2*)(out + ((size_t)bglob       * GROUPS + g) * 64 + j0) = v0;
        *(float2*)(out + ((size_t)(bglob + 8) * GROUPS + g) * 64 + j0) = v1;
    }
}

extern "C" void kernel_launch(void* const* d_in, const int* in_sizes, int n_in,
                              void* d_out, int out_size) {
    const float* x  = (const float*)d_in[0];
    const float* W0 = (const float*)d_in[1];
    const float* b0 = (const float*)d_in[2];
    const float* W1 = (const float*)d_in[3];
    const float* b1 = (const float*)d_in[4];
    float* out = (float*)d_out;

    // b-tiles innermost (blockIdx.x) so all CTAs of a group launch adjacently:
    // x (256KB) stays L2-resident, each W0[g]/W1[g] is read from DRAM ~once.
    dim3 grid(B_TOTAL / BT, GROUPS);
    convnn_tf32_kernel<<<grid, 256>>>(x, W0, b0, W1, b1, out);
}

// round 2
// speedup vs baseline: 1.4294x; 1.4294x over previous
#include <cuda_runtime.h>
#include <cstdint>

#define B_TOTAL 1024
#define GROUPS  2048
#define STRIDE  68   // smem row stride (words): bank = (4*row + col) % 32 -> conflict-free frag loads

__device__ __forceinline__ uint32_t f2tf32(float f) {
    uint32_t u;
    asm("cvt.rna.tf32.f32 %0, %1;" : "=r"(u) : "f"(f));
    return u;
}

__device__ __forceinline__ void mma_tf32(float& d0, float& d1, float& d2, float& d3,
                                         uint32_t a0, uint32_t a1, uint32_t a2, uint32_t a3,
                                         uint32_t b0, uint32_t b1) {
    asm volatile("mma.sync.aligned.m16n8k8.row.col.f32.tf32.tf32.f32 "
                 "{%0,%1,%2,%3}, {%4,%5,%6,%7}, {%8,%9}, {%0,%1,%2,%3};"
                 : "+f"(d0), "+f"(d1), "+f"(d2), "+f"(d3)
                 : "r"(a0), "r"(a1), "r"(a2), "r"(a3), "r"(b0), "r"(b1));
}

// One CTA per group. 8 warps: warp tile = m16 (rows) x n32 (j-cols).
// Both layers' weight fragments live in registers (loaded once per CTA);
// CTA loops over all 16 b-tiles of 64 rows. Only X staging, A-frag reads,
// and the h round-trip touch shared memory.
__global__ __launch_bounds__(256, 1) void convnn_persist_kernel(
    const float* __restrict__ x,  const float* __restrict__ W0,
    const float* __restrict__ b0, const float* __restrict__ W1,
    const float* __restrict__ b1, float* __restrict__ out)
{
    __shared__ uint32_t sbuf[64 * STRIDE];  // W staging, then per-iter X tile / h tile (tf32)
    __shared__ float    sB0[64];
    __shared__ float    sB1[64];

    const int g    = blockIdx.x;
    const int tid  = threadIdx.x;
    const int lane = tid & 31;
    const int warp = tid >> 5;
    const int gid  = lane >> 2;   // 0..7
    const int tig  = lane & 3;    // 0..3
    const int mrow  = (warp & 3) * 16;   // 4 m-subtiles of 16 rows
    const int jbase = (warp >> 2) * 32;  // 2 n-halves of 32 cols

    const int r  = tid >> 4;          // 0..15
    const int c4 = (tid & 15) << 2;   // 0,4,...,60

    // ---- stage W0/W1 into smem once, load fragments into registers ----
    uint32_t wf[2][4][8][2];  // [layer][j-subtile][k-chunk][2]
    #pragma unroll
    for (int layer = 0; layer < 2; layer++) {
        const float* W = (layer ? W1 : W0) + (size_t)g * 64 * 64;
        #pragma unroll
        for (int rr = 0; rr < 4; rr++) {
            const int row = r + rr * 16;
            float4 w = *(const float4*)(W + (size_t)row * 64 + c4);
            uint32_t* d = &sbuf[row * STRIDE + c4];
            d[0] = f2tf32(w.x); d[1] = f2tf32(w.y);
            d[2] = f2tf32(w.z); d[3] = f2tf32(w.w);
        }
        __syncthreads();
        #pragma unroll
        for (int s = 0; s < 4; s++) {
            const int jr = (jbase + s * 8 + gid) * STRIDE;
            #pragma unroll
            for (int kc = 0; kc < 8; kc++) {
                wf[layer][s][kc][0] = sbuf[jr + kc * 8 + tig];
                wf[layer][s][kc][1] = sbuf[jr + kc * 8 + tig + 4];
            }
        }
        __syncthreads();
    }
    if (tid < 64)       sB0[tid]      = b0[(size_t)g * 64 + tid];
    else if (tid < 128) sB1[tid - 64] = b1[(size_t)g * 64 + (tid - 64)];
    // biases read only after later __syncthreads barriers

    // ---- prefetch first X tile into registers ----
    float4 px[4];
    #pragma unroll
    for (int rr = 0; rr < 4; rr++)
        px[rr] = *(const float4*)(x + (size_t)(r + rr * 16) * 64 + c4);

    for (int it = 0; it < 16; it++) {
        // store X tile (tf32) into sbuf (safe: all readers synced)
        #pragma unroll
        for (int rr = 0; rr < 4; rr++) {
            const int row = r + rr * 16;
            uint32_t* d = &sbuf[row * STRIDE + c4];
            d[0] = f2tf32(px[rr].x); d[1] = f2tf32(px[rr].y);
            d[2] = f2tf32(px[rr].z); d[3] = f2tf32(px[rr].w);
        }
        __syncthreads();

        // prefetch next tile (latency hidden under layer-0 mma)
        if (it < 15) {
            #pragma unroll
            for (int rr = 0; rr < 4; rr++)
                px[rr] = *(const float4*)(x + (size_t)((it + 1) * 64 + r + rr * 16) * 64 + c4);
        }

        float acc[4][4];
        #pragma unroll
        for (int s = 0; s < 4; s++)
            #pragma unroll
            for (int i = 0; i < 4; i++) acc[s][i] = 0.f;

        // ===== Layer 0: h = leaky(X * W0^T + b0) =====
        #pragma unroll
        for (int kc = 0; kc < 8; kc++) {
            const int k0 = kc * 8;
            const uint32_t a0 = sbuf[(mrow + gid)     * STRIDE + k0 + tig];
            const uint32_t a1 = sbuf[(mrow + gid + 8) * STRIDE + k0 + tig];
            const uint32_t a2 = sbuf[(mrow + gid)     * STRIDE + k0 + tig + 4];
            const uint32_t a3 = sbuf[(mrow + gid + 8) * STRIDE + k0 + tig + 4];
            #pragma unroll
            for (int s = 0; s < 4; s++)
                mma_tf32(acc[s][0], acc[s][1], acc[s][2], acc[s][3],
                         a0, a1, a2, a3, wf[0][s][kc][0], wf[0][s][kc][1]);
        }
        __syncthreads();  // all X reads complete before h overwrites sbuf

        // epilogue 0: bias + LeakyReLU(0.2), write h (tf32) into sbuf
        #pragma unroll
        for (int s = 0; s < 4; s++) {
            const int j0 = jbase + s * 8 + 2 * tig;
            const float bj0 = sB0[j0], bj1 = sB0[j0 + 1];
            float h00 = acc[s][0] + bj0; h00 = (h00 > 0.f) ? h00 : 0.2f * h00;
            float h01 = acc[s][1] + bj1; h01 = (h01 > 0.f) ? h01 : 0.2f * h01;
            float h10 = acc[s][2] + bj0; h10 = (h10 > 0.f) ? h10 : 0.2f * h10;
            float h11 = acc[s][3] + bj1; h11 = (h11 > 0.f) ? h11 : 0.2f * h11;
            sbuf[(mrow + gid)     * STRIDE + j0]     = f2tf32(h00);
            sbuf[(mrow + gid)     * STRIDE + j0 + 1] = f2tf32(h01);
            sbuf[(mrow + gid + 8) * STRIDE + j0]     = f2tf32(h10);
            sbuf[(mrow + gid + 8) * STRIDE + j0 + 1] = f2tf32(h11);
        }
        __syncthreads();  // h fully visible

        // ===== Layer 1: out = h * W1^T + b1 =====
        #pragma unroll
        for (int s = 0; s < 4; s++)
            #pragma unroll
            for (int i = 0; i < 4; i++) acc[s][i] = 0.f;

        #pragma unroll
        for (int kc = 0; kc < 8; kc++) {
            const int k0 = kc * 8;
            const uint32_t a0 = sbuf[(mrow + gid)     * STRIDE + k0 + tig];
            const uint32_t a1 = sbuf[(mrow + gid + 8) * STRIDE + k0 + tig];
            const uint32_t a2 = sbuf[(mrow + gid)     * STRIDE + k0 + tig + 4];
            const uint32_t a3 = sbuf[(mrow + gid + 8) * STRIDE + k0 + tig + 4];
            #pragma unroll
            for (int s = 0; s < 4; s++)
                mma_tf32(acc[s][0], acc[s][1], acc[s][2], acc[s][3],
                         a0, a1, a2, a3, wf[1][s][kc][0], wf[1][s][kc][1]);
        }
        __syncthreads();  // h reads complete before next iter's X store

        // epilogue 1: bias, write out as float2
        const int bglob = it * 64 + mrow + gid;
        #pragma unroll
        for (int s = 0; s < 4; s++) {
            const int j0 = jbase + s * 8 + 2 * tig;
            const float bj0 = sB1[j0], bj1 = sB1[j0 + 1];
            float2 v0 = make_float2(acc[s][0] + bj0, acc[s][1] + bj1);
            float2 v1 = make_float2(acc[s][2] + bj0, acc[s][3] + bj1);
            *(float2*)(out + ((size_t)bglob       * GROUPS + g) * 64 + j0) = v0;
            *(float2*)(out + ((size_t)(bglob + 8) * GROUPS + g) * 64 + j0) = v1;
        }
    }
}

extern "C" void kernel_launch(void* const* d_in, const int* in_sizes, int n_in,
                              void* d_out, int out_size) {
    const float* x  = (const float*)d_in[0];
    const float* W0 = (const float*)d_in[1];
    const float* b0 = (const float*)d_in[2];
    const float* W1 = (const float*)d_in[3];
    const float* b1 = (const float*)d_in[4];
    float* out = (float*)d_out;

    convnn_persist_kernel<<<GROUPS, 256>>>(x, W0, b0, W1, b1, out);
}